// round 5
// baseline (speedup 1.0000x reference)
#include <cuda_runtime.h>

// B3-spline à-trous UWT, J=3, split into 3 single-level kernels.
// (8,1024,1024) fp32 -> (8,4,1024,1024) fp32 = [w1,w2,w3,c3]
//
// Each kernel: vertical 5-tap conv (dilation D) read straight from gmem via
// phase-chain sliding register windows into a small smem row buffer (one
// barrier), then horizontal conv from smem + re-read of the level input at
// center (L2-hot) to emit w = in - c and c, fully coalesced.
// Phase-1 units = (vec-col, phase, chain-seg of 4 outputs): 272/288/320 units
// for NT=256 -> all threads active, and D=4 redundancy drops 3.0x -> 2.0x.
// Reflect indexing per level reproduces the reference's reflect padding.
// c1 lives in out ch3 (overwritten by c3 later), c2 in a static scratch.

namespace {

constexpr int NT  = 256;
constexpr int IMG = 1024;
constexpr size_t CHS = (size_t)IMG * IMG;

constexpr float W0 = 0.0625f;  // 1/16
constexpr float W1 = 0.25f;    // 1/4
constexpr float W2 = 0.375f;   // 3/8

__device__ float g_scratch[8u * 1024u * 1024u];  // 32MB c2 carrier

__device__ __forceinline__ int refl(int g) {
    g = g < 0 ? -g : g;
    return g >= IMG ? 2 * IMG - 2 - g : g;
}
__device__ __forceinline__ float b3s(float a, float b, float c, float d, float e) {
    return fmaf(c, W2, fmaf(b + d, W1, (a + e) * W0));
}
__device__ __forceinline__ float4 b3v(const float4& a, const float4& b,
                                      const float4& c, const float4& d,
                                      const float4& e) {
    float4 r;
    r.x = b3s(a.x, b.x, c.x, d.x, e.x);
    r.y = b3s(a.y, b.y, c.y, d.y, e.y);
    r.z = b3s(a.z, b.z, c.z, d.z, e.z);
    r.w = b3s(a.w, b.w, c.w, d.w, e.w);
    return r;
}
__device__ __forceinline__ void st4(float* p, float4 v) {
    *reinterpret_cast<float4*>(p) = v;
}
__device__ __forceinline__ float4 ld4(const float* p) {
    return *reinterpret_cast<const float4*>(p);
}

// 16B gmem load; for D==1 the column base is only 8B aligned -> two float2.
template <int D>
__device__ __forceinline__ float4 ldg4(const float* p) {
    if (D == 1) {
        const float2 a = __ldg(reinterpret_cast<const float2*>(p));
        const float2 b = __ldg(reinterpret_cast<const float2*>(p + 2));
        return make_float4(a.x, a.y, b.x, b.y);
    } else {
        return __ldg(reinterpret_cast<const float4*>(p));
    }
}

// Scalar-gather float4 for border columns.
__device__ __forceinline__ float4 gath(const float* row, const int cc[4]) {
    return make_float4(__ldg(row + cc[0]), __ldg(row + cc[1]),
                       __ldg(row + cc[2]), __ldg(row + cc[3]));
}

// One wavelet level, dilation D. NVEC = (64+4D)/4 vec-cols, PB = smem pitch
// (% 8 == 4). SSRC/SDST: source/coeff-dest is the static scratch.
template <int D, int NVEC, int PB, bool SSRC, bool SDST>
__global__ void __launch_bounds__(NT, 6)
lvl_kernel(const float* __restrict__ src, size_t sstride,
           float* __restrict__ wdst,
           float* __restrict__ cdst, size_t cstride) {
    __shared__ float B[64 * PB];

    const int tid = threadIdx.x;
    const int gc0 = blockIdx.x * 64;
    const int gr0 = blockIdx.y * 64;
    const int b   = blockIdx.z;

    const float* s = SSRC ? (g_scratch + (size_t)b * CHS)
                          : (src + (size_t)b * sstride);

    // ---- phase 1: vertical conv (gmem -> smem B) ----
    // unit = (vec-col, phase p, chain seg of 4 outputs stepping D rows)
    const bool colint = (gc0 >= 2 * D) && (gc0 + 64 + 2 * D <= IMG);
    constexpr int UNITS = NVEC * 16;  // 16 = D * (64 / (4*D))
    for (int u = tid; u < UNITS; u += NT) {
        const int vc = u % NVEC;
        const int t  = u / NVEC;        // 0..15
        const int p  = t % D;
        const int cs = t / D;           // 0 .. 16/D - 1
        int r = p + cs * 4 * D;         // first output row of this chain seg
        const int cb = gc0 - 2 * D + 4 * vc;
        float* Bp = B + 4 * vc;
        if (colint) {
            const float* cp = s + cb;
            float4 v0 = ldg4<D>(cp + (size_t)refl(gr0 + r - 2 * D) * IMG);
            float4 v1 = ldg4<D>(cp + (size_t)refl(gr0 + r - D) * IMG);
            float4 v2 = ldg4<D>(cp + (size_t)refl(gr0 + r) * IMG);
            float4 v3 = ldg4<D>(cp + (size_t)refl(gr0 + r + D) * IMG);
#pragma unroll
            for (int k = 0; k < 4; ++k, r += D) {
                const float4 v4 =
                    ldg4<D>(cp + (size_t)refl(gr0 + r + 2 * D) * IMG);
                st4(Bp + r * PB, b3v(v0, v1, v2, v3, v4));
                v0 = v1; v1 = v2; v2 = v3; v3 = v4;
            }
        } else {
            int cc[4];
#pragma unroll
            for (int j = 0; j < 4; ++j) {
                int c = cb + j;
                c = c < 0 ? -c : c;
                cc[j] = c >= IMG ? 2 * IMG - 2 - c : c;
            }
            float4 v0 = gath(s + (size_t)refl(gr0 + r - 2 * D) * IMG, cc);
            float4 v1 = gath(s + (size_t)refl(gr0 + r - D) * IMG, cc);
            float4 v2 = gath(s + (size_t)refl(gr0 + r) * IMG, cc);
            float4 v3 = gath(s + (size_t)refl(gr0 + r + D) * IMG, cc);
#pragma unroll
            for (int k = 0; k < 4; ++k, r += D) {
                const float4 v4 =
                    gath(s + (size_t)refl(gr0 + r + 2 * D) * IMG, cc);
                st4(Bp + r * PB, b3v(v0, v1, v2, v3, v4));
                v0 = v1; v1 = v2; v2 = v3; v3 = v4;
            }
        }
    }
    __syncthreads();

    // ---- phase 2: horizontal conv + diff + coalesced store ----
    const int lane = tid & 31, warp = tid >> 5;
    const int v = lane & 15, sub = lane >> 4;
    float* wd = wdst + (size_t)b * 4 * CHS;
    float* cd = SDST ? (g_scratch + (size_t)b * CHS)
                     : (cdst + (size_t)b * cstride);
#pragma unroll
    for (int i = 0; i < 4; ++i) {
        const int rr = i * 16 + warp * 2 + sub;
        const float* Bp = B + rr * PB + 4 * v;
        float w[4 * (D + 1)];
#pragma unroll
        for (int k = 0; k <= D; ++k) {
            const float4 t = ld4(Bp + 4 * k);
            w[4 * k + 0] = t.x; w[4 * k + 1] = t.y;
            w[4 * k + 2] = t.z; w[4 * k + 3] = t.w;
        }
        float4 o;
        o.x = b3s(w[0], w[D],     w[2 * D],     w[3 * D],     w[4 * D]);
        o.y = b3s(w[1], w[1 + D], w[1 + 2 * D], w[1 + 3 * D], w[1 + 4 * D]);
        o.z = b3s(w[2], w[2 + D], w[2 + 2 * D], w[2 + 3 * D], w[2 + 4 * D]);
        o.w = b3s(w[3], w[3 + D], w[3 + 2 * D], w[3 + 3 * D], w[3 + 4 * D]);

        const size_t go = (size_t)(gr0 + rr) * IMG + gc0 + 4 * v;
        const float4 a = __ldg(reinterpret_cast<const float4*>(s + go));
        st4(wd + go, make_float4(a.x - o.x, a.y - o.y, a.z - o.z, a.w - o.w));
        st4(cd + go, o);
    }
}

}  // namespace

extern "C" void kernel_launch(void* const* d_in, const int* in_sizes, int n_in,
                              void* d_out, int out_size) {
    (void)in_sizes; (void)n_in; (void)out_size;
    const float* x = (const float*)d_in[0];
    float* out = (float*)d_out;

    dim3 grid(IMG / 64, IMG / 64, 8);  // 16 x 16 x 8

    // K1 (d=1): x -> w1 (ch0), c1 -> out ch3
    lvl_kernel<1, 17, 68, false, false><<<grid, NT>>>(
        x, CHS, out, out + 3 * CHS, 4 * CHS);

    // K2 (d=2): c1 (ch3) -> w2 (ch1), c2 -> scratch
    lvl_kernel<2, 18, 76, false, true><<<grid, NT>>>(
        out + 3 * CHS, 4 * CHS, out + CHS, nullptr, 0);

    // K3 (d=4): c2 (scratch) -> w3 (ch2), c3 -> out ch3
    lvl_kernel<4, 20, 84, true, false><<<grid, NT>>>(
        nullptr, 0, out + 2 * CHS, out + 3 * CHS, 4 * CHS);
}

// round 6
// speedup vs baseline: 1.1512x; 1.1512x over previous
#include <cuda_runtime.h>

// B3-spline à-trous UWT, J=3, 3 single-level kernels, warp-autonomous strips.
// (8,1024,1024) fp32 -> (8,4,1024,1024) fp32 = [w1,w2,w3,c3]
//
// Each warp owns an 8-row x 64-col output strip: vertical 5-tap conv (dil. D)
// from gmem via phase-chain sliding windows into a PRIVATE smem strip,
// __syncwarp, then horizontal conv + diff + coalesced store. No __syncthreads
// anywhere -> no block-wide barrier idle. Phase chains give 1.0x load
// redundancy for D=2,4 (1.33x for D=1).
// Reflect indexing per level reproduces the reference's reflect padding.
// c1 lives in out ch3 (overwritten by c3 later), c2 in a static scratch.

namespace {

constexpr int NT  = 256;
constexpr int IMG = 1024;
constexpr size_t CHS = (size_t)IMG * IMG;

constexpr float W0 = 0.0625f;
constexpr float W1 = 0.25f;
constexpr float W2 = 0.375f;

__device__ float g_scratch[8u * 1024u * 1024u];  // 32MB c2 carrier

__device__ __forceinline__ int refl(int g) {
    g = g < 0 ? -g : g;
    return g >= IMG ? 2 * IMG - 2 - g : g;
}
__device__ __forceinline__ float b3s(float a, float b, float c, float d, float e) {
    return fmaf(c, W2, fmaf(b + d, W1, (a + e) * W0));
}
__device__ __forceinline__ float4 b3v(const float4& a, const float4& b,
                                      const float4& c, const float4& d,
                                      const float4& e) {
    float4 r;
    r.x = b3s(a.x, b.x, c.x, d.x, e.x);
    r.y = b3s(a.y, b.y, c.y, d.y, e.y);
    r.z = b3s(a.z, b.z, c.z, d.z, e.z);
    r.w = b3s(a.w, b.w, c.w, d.w, e.w);
    return r;
}
__device__ __forceinline__ void st4(float* p, float4 v) {
    *reinterpret_cast<float4*>(p) = v;
}
__device__ __forceinline__ float4 ld4(const float* p) {
    return *reinterpret_cast<const float4*>(p);
}

// 16B gmem load; for D==1 the column base is only 8B aligned -> two float2.
template <int D>
__device__ __forceinline__ float4 ldg4(const float* p) {
    if (D == 1) {
        const float2 a = __ldg(reinterpret_cast<const float2*>(p));
        const float2 b = __ldg(reinterpret_cast<const float2*>(p + 2));
        return make_float4(a.x, a.y, b.x, b.y);
    } else {
        return __ldg(reinterpret_cast<const float4*>(p));
    }
}

__device__ __forceinline__ float4 gath(const float* row, const int cc[4]) {
    return make_float4(__ldg(row + cc[0]), __ldg(row + cc[1]),
                       __ldg(row + cc[2]), __ldg(row + cc[3]));
}

// One wavelet level, dilation D. NVEC = (64+4D)/4 vec-cols, PB = smem pitch
// (% 8 == 4), L = chain length (outputs per phase-chain unit).
// SSRC/SDST: source/coeff-dest is the static scratch.
template <int D, int NVEC, int PB, int L, bool SSRC, bool SDST>
__global__ void __launch_bounds__(NT, 6)
lvl_kernel(const float* __restrict__ src, size_t sstride,
           float* __restrict__ wdst,
           float* __restrict__ cdst, size_t cstride) {
    __shared__ float B[8 * 8 * PB];  // 8 warps x (8 rows x PB)

    const int tid  = threadIdx.x;
    const int lane = tid & 31;
    const int warp = tid >> 5;
    const int gc0 = blockIdx.x * 64;
    const int gr0 = blockIdx.y * 64;
    const int b   = blockIdx.z;

    const float* s = SSRC ? (g_scratch + (size_t)b * CHS)
                          : (src + (size_t)b * sstride);

    const int wr0 = gr0 + warp * 8;       // first output row of this strip
    float* Bw = B + warp * 8 * PB;        // private smem strip

    // ---- phase 1: vertical conv (gmem -> private smem strip) ----
    // unit = (vec-col, phase-chain of L outputs stepping D rows)
    const bool colint = (gc0 >= 2 * D) && (gc0 + 64 + 2 * D <= IMG);
    constexpr int CPC   = 8 / L;          // chains per column
    constexpr int UNITS = NVEC * CPC;     // 34 / 36 / 80
    for (int u = lane; u < UNITS; u += 32) {
        const int vc = u % NVEC;
        const int t  = u / NVEC;          // 0..CPC-1
        const int p  = t % D;
        const int cs = t / D;
        int r = p + cs * L * D;           // local output row (0..7)
        const int cb = gc0 - 2 * D + 4 * vc;
        float* Bp = Bw + 4 * vc;
        if (colint) {
            const float* cp = s + cb;
            float4 v0 = ldg4<D>(cp + (size_t)refl(wr0 + r - 2 * D) * IMG);
            float4 v1 = ldg4<D>(cp + (size_t)refl(wr0 + r - D) * IMG);
            float4 v2 = ldg4<D>(cp + (size_t)refl(wr0 + r) * IMG);
            float4 v3 = ldg4<D>(cp + (size_t)refl(wr0 + r + D) * IMG);
#pragma unroll
            for (int k = 0; k < L; ++k, r += D) {
                const float4 v4 =
                    ldg4<D>(cp + (size_t)refl(wr0 + r + 2 * D) * IMG);
                st4(Bp + r * PB, b3v(v0, v1, v2, v3, v4));
                v0 = v1; v1 = v2; v2 = v3; v3 = v4;
            }
        } else {
            int cc[4];
#pragma unroll
            for (int j = 0; j < 4; ++j) {
                int c = cb + j;
                c = c < 0 ? -c : c;
                cc[j] = c >= IMG ? 2 * IMG - 2 - c : c;
            }
            float4 v0 = gath(s + (size_t)refl(wr0 + r - 2 * D) * IMG, cc);
            float4 v1 = gath(s + (size_t)refl(wr0 + r - D) * IMG, cc);
            float4 v2 = gath(s + (size_t)refl(wr0 + r) * IMG, cc);
            float4 v3 = gath(s + (size_t)refl(wr0 + r + D) * IMG, cc);
#pragma unroll
            for (int k = 0; k < L; ++k, r += D) {
                const float4 v4 =
                    gath(s + (size_t)refl(wr0 + r + 2 * D) * IMG, cc);
                st4(Bp + r * PB, b3v(v0, v1, v2, v3, v4));
                v0 = v1; v1 = v2; v2 = v3; v3 = v4;
            }
        }
    }
    __syncwarp();

    // ---- phase 2: horizontal conv + diff + coalesced store ----
    const int v = lane & 15, sub = lane >> 4;
    float* wd = wdst + (size_t)b * 4 * CHS;
    float* cd = SDST ? (g_scratch + (size_t)b * CHS)
                     : (cdst + (size_t)b * cstride);
#pragma unroll
    for (int i = 0; i < 4; ++i) {
        const int rr = i * 2 + sub;       // local row 0..7
        const float* Bp = Bw + rr * PB + 4 * v;
        float w[4 * (D + 1)];
#pragma unroll
        for (int k = 0; k <= D; ++k) {
            const float4 t = ld4(Bp + 4 * k);
            w[4 * k + 0] = t.x; w[4 * k + 1] = t.y;
            w[4 * k + 2] = t.z; w[4 * k + 3] = t.w;
        }
        float4 o;
        o.x = b3s(w[0], w[D],     w[2 * D],     w[3 * D],     w[4 * D]);
        o.y = b3s(w[1], w[1 + D], w[1 + 2 * D], w[1 + 3 * D], w[1 + 4 * D]);
        o.z = b3s(w[2], w[2 + D], w[2 + 2 * D], w[2 + 3 * D], w[2 + 4 * D]);
        o.w = b3s(w[3], w[3 + D], w[3 + 2 * D], w[3 + 3 * D], w[3 + 4 * D]);

        const size_t go = (size_t)(wr0 + rr) * IMG + gc0 + 4 * v;
        const float4 a = __ldg(reinterpret_cast<const float4*>(s + go));
        st4(wd + go, make_float4(a.x - o.x, a.y - o.y, a.z - o.z, a.w - o.w));
        st4(cd + go, o);
    }
}

}  // namespace

extern "C" void kernel_launch(void* const* d_in, const int* in_sizes, int n_in,
                              void* d_out, int out_size) {
    (void)in_sizes; (void)n_in; (void)out_size;
    const float* x = (const float*)d_in[0];
    float* out = (float*)d_out;

    dim3 grid(IMG / 64, IMG / 64, 8);  // 16 x 16 x 8

    // K1 (d=1): x -> w1 (ch0), c1 -> out ch3
    lvl_kernel<1, 17, 68, 4, false, false><<<grid, NT>>>(
        x, CHS, out, out + 3 * CHS, 4 * CHS);

    // K2 (d=2): c1 (ch3) -> w2 (ch1), c2 -> scratch
    lvl_kernel<2, 18, 76, 4, false, true><<<grid, NT>>>(
        out + 3 * CHS, 4 * CHS, out + CHS, nullptr, 0);

    // K3 (d=4): c2 (scratch) -> w3 (ch2), c3 -> out ch3
    lvl_kernel<4, 20, 84, 2, true, false><<<grid, NT>>>(
        nullptr, 0, out + 2 * CHS, out + 3 * CHS, 4 * CHS);
}

// round 7
// speedup vs baseline: 1.2308x; 1.0691x over previous
#include <cuda_runtime.h>

// B3-spline à-trous UWT, J=3. ONE kernel launch: grid z = level*8 + image.
// (8,1024,1024) fp32 -> (8,4,1024,1024) fp32 = [w1,w2,w3,c3]
//
// Per block: one 64x64 tile of one level. Warp-autonomous 8-row strips:
// vertical conv from gmem (aligned LDG.128 sliding rings / phase chains) into
// a private smem strip, __syncwarp, horizontal conv + diff + coalesced store.
// Levels synchronize through per-image release/acquire counters (K2 gates on
// K1-of-its-image complete, K3 on K2). Dispatch is bid-ordered so gates only
// wait on earlier blocks -> deadlock-free; counters self-reset (graph-safe).
// c1 lives in out ch3 (overwritten by c3), c2 in a static scratch buffer.

namespace {

constexpr int NT  = 256;
constexpr int IMG = 1024;
constexpr size_t CHS = (size_t)IMG * IMG;

constexpr float W0 = 0.0625f;
constexpr float W1 = 0.25f;
constexpr float W2 = 0.375f;

__device__ float g_scratch[8u * 1024u * 1024u];  // 32MB c2 carrier
__device__ unsigned g_done[3][8];                // zero-init; self-resetting

__device__ __forceinline__ int refl(int g) {
    g = g < 0 ? -g : g;
    return g >= IMG ? 2 * IMG - 2 - g : g;
}
__device__ __forceinline__ float b3s(float a, float b, float c, float d, float e) {
    return fmaf(c, W2, fmaf(b + d, W1, (a + e) * W0));
}
__device__ __forceinline__ float4 b3v(const float4& a, const float4& b,
                                      const float4& c, const float4& d,
                                      const float4& e) {
    float4 r;
    r.x = b3s(a.x, b.x, c.x, d.x, e.x);
    r.y = b3s(a.y, b.y, c.y, d.y, e.y);
    r.z = b3s(a.z, b.z, c.z, d.z, e.z);
    r.w = b3s(a.w, b.w, c.w, d.w, e.w);
    return r;
}
__device__ __forceinline__ void st4(float* p, float4 v) {
    *reinterpret_cast<float4*>(p) = v;
}
__device__ __forceinline__ float4 ld4(const float* p) {
    return *reinterpret_cast<const float4*>(p);
}
__device__ __forceinline__ float4 lg4(const float* p) {
    return __ldg(reinterpret_cast<const float4*>(p));
}
__device__ __forceinline__ float4 gath(const float* row, const int cc[4]) {
    return make_float4(__ldg(row + cc[0]), __ldg(row + cc[1]),
                       __ldg(row + cc[2]), __ldg(row + cc[3]));
}

// One 64x64 tile of one level, dilation D. H = col halo (4 for D=1, else 2D,
// always 16B-aligned), NVEC = (64+2H)/4 vec-cols, PB = smem row pitch.
template <int D, int NVEC, int PB>
__device__ __forceinline__ void level_tile(const float* __restrict__ s,
                                           float* __restrict__ wd,
                                           float* __restrict__ cd,
                                           float* __restrict__ B) {
    const int tid  = threadIdx.x;
    const int lane = tid & 31;
    const int warp = tid >> 5;
    const int gc0 = blockIdx.x * 64;
    const int gr0 = blockIdx.y * 64;
    const int wr0 = gr0 + warp * 8;
    float* Bw = B + warp * (8 * PB);
    constexpr int H = (D == 1) ? 4 : 2 * D;
    const bool colint = (gc0 >= H) && (gc0 + 64 + H <= IMG);

    // ---- phase 1: vertical conv (gmem -> private smem strip) ----
    if (D == 1) {
        // one full 12-row sliding ring per lane (18 active lanes, 1 iteration)
        if (lane < NVEC) {
            const int cb = gc0 - H + 4 * lane;
            float* Bp = Bw + 4 * lane;
            if (colint) {
                const float* cp = s + cb;
                float4 v0 = lg4(cp + (size_t)refl(wr0 - 2) * IMG);
                float4 v1 = lg4(cp + (size_t)refl(wr0 - 1) * IMG);
                float4 v2 = lg4(cp + (size_t)refl(wr0) * IMG);
                float4 v3 = lg4(cp + (size_t)refl(wr0 + 1) * IMG);
#pragma unroll
                for (int k = 0; k < 8; ++k) {
                    const float4 v4 = lg4(cp + (size_t)refl(wr0 + 2 + k) * IMG);
                    st4(Bp + k * PB, b3v(v0, v1, v2, v3, v4));
                    v0 = v1; v1 = v2; v2 = v3; v3 = v4;
                }
            } else {
                int cc[4];
#pragma unroll
                for (int j = 0; j < 4; ++j) {
                    int c = cb + j;
                    c = c < 0 ? -c : c;
                    cc[j] = c >= IMG ? 2 * IMG - 2 - c : c;
                }
                float4 v0 = gath(s + (size_t)refl(wr0 - 2) * IMG, cc);
                float4 v1 = gath(s + (size_t)refl(wr0 - 1) * IMG, cc);
                float4 v2 = gath(s + (size_t)refl(wr0) * IMG, cc);
                float4 v3 = gath(s + (size_t)refl(wr0 + 1) * IMG, cc);
#pragma unroll
                for (int k = 0; k < 8; ++k) {
                    const float4 v4 =
                        gath(s + (size_t)refl(wr0 + 2 + k) * IMG, cc);
                    st4(Bp + k * PB, b3v(v0, v1, v2, v3, v4));
                    v0 = v1; v1 = v2; v2 = v3; v3 = v4;
                }
            }
        }
    } else {
        // phase chains: unit = (vec-col, dilation phase), chain of L outputs
        constexpr int L = (D == 2) ? 4 : 2;
        constexpr int CPC = 8 / L;          // == D
        constexpr int UNITS = NVEC * CPC;   // 36 / 80
        for (int u = lane; u < UNITS; u += 32) {
            const int vc = u % NVEC;
            const int p  = u / NVEC;
            int r = p;                       // local output row start
            const int cb = gc0 - H + 4 * vc;
            float* Bp = Bw + 4 * vc;
            if (colint) {
                const float* cp = s + cb;
                float4 v0 = lg4(cp + (size_t)refl(wr0 + r - 2 * D) * IMG);
                float4 v1 = lg4(cp + (size_t)refl(wr0 + r - D) * IMG);
                float4 v2 = lg4(cp + (size_t)refl(wr0 + r) * IMG);
                float4 v3 = lg4(cp + (size_t)refl(wr0 + r + D) * IMG);
#pragma unroll
                for (int k = 0; k < L; ++k, r += D) {
                    const float4 v4 =
                        lg4(cp + (size_t)refl(wr0 + r + 2 * D) * IMG);
                    st4(Bp + r * PB, b3v(v0, v1, v2, v3, v4));
                    v0 = v1; v1 = v2; v2 = v3; v3 = v4;
                }
            } else {
                int cc[4];
#pragma unroll
                for (int j = 0; j < 4; ++j) {
                    int c = cb + j;
                    c = c < 0 ? -c : c;
                    cc[j] = c >= IMG ? 2 * IMG - 2 - c : c;
                }
                float4 v0 = gath(s + (size_t)refl(wr0 + r - 2 * D) * IMG, cc);
                float4 v1 = gath(s + (size_t)refl(wr0 + r - D) * IMG, cc);
                float4 v2 = gath(s + (size_t)refl(wr0 + r) * IMG, cc);
                float4 v3 = gath(s + (size_t)refl(wr0 + r + D) * IMG, cc);
#pragma unroll
                for (int k = 0; k < L; ++k, r += D) {
                    const float4 v4 =
                        gath(s + (size_t)refl(wr0 + r + 2 * D) * IMG, cc);
                    st4(Bp + r * PB, b3v(v0, v1, v2, v3, v4));
                    v0 = v1; v1 = v2; v2 = v3; v3 = v4;
                }
            }
        }
    }
    __syncwarp();

    // ---- phase 2: horizontal conv + diff + coalesced store ----
    const int v = lane & 15, sub = lane >> 4;
    constexpr int BL = H / 4;           // float4 blocks of left halo
    constexpr int NV = 2 * BL + 1;      // window float4 count (3/3/5)
    constexpr int C  = H;               // center float offset in window
#pragma unroll
    for (int i = 0; i < 4; ++i) {
        const int rr = i * 2 + sub;
        const float* Bp = Bw + rr * PB + 4 * v;
        float w[4 * NV];
#pragma unroll
        for (int k = 0; k < NV; ++k) {
            const float4 t = ld4(Bp + 4 * k);
            w[4 * k + 0] = t.x; w[4 * k + 1] = t.y;
            w[4 * k + 2] = t.z; w[4 * k + 3] = t.w;
        }
        float4 o;
        o.x = b3s(w[C - 2 * D],     w[C - D],     w[C],     w[C + D],     w[C + 2 * D]);
        o.y = b3s(w[C + 1 - 2 * D], w[C + 1 - D], w[C + 1], w[C + 1 + D], w[C + 1 + 2 * D]);
        o.z = b3s(w[C + 2 - 2 * D], w[C + 2 - D], w[C + 2], w[C + 2 + D], w[C + 2 + 2 * D]);
        o.w = b3s(w[C + 3 - 2 * D], w[C + 3 - D], w[C + 3], w[C + 3 + D], w[C + 3 + 2 * D]);

        const size_t go = (size_t)(wr0 + rr) * IMG + gc0 + 4 * v;
        const float4 a = lg4(s + go);
        st4(wd + go, make_float4(a.x - o.x, a.y - o.y, a.z - o.z, a.w - o.w));
        st4(cd + go, o);
    }
}

__device__ __forceinline__ void gate(unsigned* ctr) {
    if (threadIdx.x == 0) {
        while (atomicAdd(ctr, 0u) < 256u) __nanosleep(64);
        __threadfence();
    }
    __syncthreads();
}
__device__ __forceinline__ void finish(unsigned* ctr) {
    __threadfence();
    __syncthreads();
    if (threadIdx.x == 0) atomicAdd(ctr, 1u);
}

}  // namespace

__global__ void __launch_bounds__(NT, 5)
uwt_all_kernel(const float* __restrict__ x, float* __restrict__ out) {
    __shared__ float B[8 * 8 * 80];  // max strip pitch (D=4)
    const int z = blockIdx.z;
    const int l = z >> 3;
    const int b = z & 7;

    if (l == 0) {
        level_tile<1, 18, 72>(x + (size_t)b * CHS,
                              out + (size_t)(4 * b + 0) * CHS,
                              out + (size_t)(4 * b + 3) * CHS, B);
        finish(&g_done[0][b]);
    } else if (l == 1) {
        gate(&g_done[0][b]);
        level_tile<2, 18, 72>(out + (size_t)(4 * b + 3) * CHS,
                              out + (size_t)(4 * b + 1) * CHS,
                              g_scratch + (size_t)b * CHS, B);
        finish(&g_done[1][b]);
    } else {
        gate(&g_done[1][b]);
        level_tile<4, 20, 80>(g_scratch + (size_t)b * CHS,
                              out + (size_t)(4 * b + 2) * CHS,
                              out + (size_t)(4 * b + 3) * CHS, B);
        __threadfence();
        __syncthreads();
        if (threadIdx.x == 0) {
            if (atomicAdd(&g_done[2][b], 1u) == 255u) {
                atomicExch(&g_done[0][b], 0u);  // self-reset for next replay
                atomicExch(&g_done[1][b], 0u);
                atomicExch(&g_done[2][b], 0u);
            }
        }
    }
}

extern "C" void kernel_launch(void* const* d_in, const int* in_sizes, int n_in,
                              void* d_out, int out_size) {
    (void)in_sizes; (void)n_in; (void)out_size;
    const float* x = (const float*)d_in[0];
    float* out = (float*)d_out;

    dim3 grid(IMG / 64, IMG / 64, 24);  // z = level*8 + image
    uwt_all_kernel<<<grid, NT>>>(x, out);
}